// round 14
// baseline (speedup 1.0000x reference)
#include <cuda_runtime.h>
#include <math.h>

#define B 2048
#define A1_PER (64*225)       // 14400
#define A2_PER (32*36)        // 1152
#define H_PER 512
#define KCB 100
#define BN_EPS 1e-5f

#define RECON_OFF 0
#define H_OFF     (B*H_PER)
#define LOSS_OFF  (2*B*H_PER)
#define LP_OFF    (2*B*H_PER + 1)

typedef unsigned long long u64;

// ---------------- device scratch ----------------
__device__ __align__(16) float g_a1[B*A1_PER];    // conv1 out [n][co][225] (pre-BN)
__device__ __align__(16) float g_a2[B*A2_PER];    // conv2 out [n][pos36][co32]
__device__ __align__(16) float g_hp[B*H_PER];     // conv3 out [n][co][16]
__device__ __align__(16) float2 g_w2p[64*16*10];  // conv2 co-pairs [ci][cp][10]
__device__ __align__(16) float2 g_w3p2[32*16*10]; // conv3 co-pairs [ci][cp][10]
__device__ float g_sum1[64], g_ssq1[64];
__device__ float g_sum2[32], g_ssq2[32];
__device__ float g_sum3[32], g_ssq3[32];
__device__ float g_cbsq[KCB];
__device__ float g_vq;

__device__ __forceinline__ float wredsum(float v) {
#pragma unroll
    for (int o = 16; o; o >>= 1) v += __shfl_down_sync(0xffffffffu, v, o);
    return v;
}
__device__ __forceinline__ u64 pack2(float x, float y) {
    u64 r; asm("mov.b64 %0, {%1,%2};" : "=l"(r) : "f"(x), "f"(y)); return r;
}
__device__ __forceinline__ u64 dup2(float x) { return pack2(x, x); }
__device__ __forceinline__ u64 fma2(u64 a, u64 b, u64 c) {
    u64 d; asm("fma.rn.f32x2 %0, %1, %2, %3;" : "=l"(d) : "l"(a), "l"(b), "l"(c)); return d;
}
__device__ __forceinline__ float2 unpack2(u64 a) {
    float2 f; asm("mov.b64 {%0,%1}, %2;" : "=f"(f.x), "=f"(f.y) : "l"(a)); return f;
}

// ---------------- conv1: self-repacking, zeroes global stats ----------------
__global__ void __launch_bounds__(256, 3) k_conv1(const float* __restrict__ x,
                                                  const float* __restrict__ w1raw,
                                                  const float* __restrict__ bias) {
    __shared__ __align__(16) float  sx[3*32*34];
    __shared__ __align__(16) float2 swp1[3*32*10];    // co-pairs [ci][cp32][10]
    __shared__ float sb[64];
    int n = blockIdx.x, tid = threadIdx.x;

    if (n == 0) {                                     // zero stat accumulators
        if (tid < 64) { g_sum1[tid] = 0.f; g_ssq1[tid] = 0.f; }
        if (tid < 32) { g_sum2[tid] = 0.f; g_ssq2[tid] = 0.f;
                        g_sum3[tid] = 0.f; g_ssq3[tid] = 0.f; }
        if (tid == 0) g_vq = 0.f;
    }

    const float4* x4 = (const float4*)(x + (size_t)n * 3072);
    for (int i = tid; i < 768; i += 256) {
        float4 v = x4[i];
        int e = i * 4, ci = e >> 10, rem = e & 1023, y = rem >> 5, xc = rem & 31;
        float* d = sx + ci*1088 + y*34 + xc;
        d[0] = v.x; d[1] = v.y; d[2] = v.z; d[3] = v.w;
    }
    // self-repack conv1 weights (tiny; L1-resident across blocks)
    for (int i = tid; i < 960; i += 256) {
        int k = i % 10, r = i / 10, ci = r / 32, cp = r % 32;
        float a = 0.f, b = 0.f;
        if (k < 9) { a = w1raw[(2*cp)*27 + ci*9 + k]; b = w1raw[(2*cp+1)*27 + ci*9 + k]; }
        swp1[i] = make_float2(a, b);
    }
    if (tid < 64) sb[tid] = bias[tid];
    __syncthreads();

    for (int it = tid; it < 1800; it += 256) {
        int pos = it % 225, cg = it / 225;
        int py2 = (pos / 15) * 2, px2 = (pos % 15) * 2;
        u64 acc[4][4];
#pragma unroll
        for (int j = 0; j < 4; j++)
#pragma unroll
            for (int p = 0; p < 4; p++) acc[j][p] = 0ull;

#pragma unroll
        for (int ci = 0; ci < 3; ci++) {
            const float* sp = sx + ci*1088 + py2*34 + px2;
            u64 pp[4][4];
#pragma unroll
            for (int rr = 0; rr < 4; rr++) {
                float2 f01 = *(const float2*)(sp + rr*34);
                float2 f23 = *(const float2*)(sp + rr*34 + 2);
                pp[rr][0] = dup2(f01.x); pp[rr][1] = dup2(f01.y);
                pp[rr][2] = dup2(f23.x); pp[rr][3] = dup2(f23.y);
            }
            const ulonglong2* wv = (const ulonglong2*)(swp1 + (ci*32 + cg*4)*10);
#pragma unroll
            for (int j = 0; j < 4; j++) {
                ulonglong2 wa = wv[j*5+0], wb = wv[j*5+1], wc = wv[j*5+2],
                           wd = wv[j*5+3], we = wv[j*5+4];
                u64 wk[9] = {wa.x, wa.y, wb.x, wb.y, wc.x, wc.y, wd.x, wd.y, we.x};
#pragma unroll
                for (int ky = 0; ky < 3; ky++)
#pragma unroll
                    for (int kx = 0; kx < 3; kx++) {
                        u64 w = wk[ky*3+kx];
                        acc[j][0] = fma2(w, pp[ky  ][kx  ], acc[j][0]);
                        acc[j][1] = fma2(w, pp[ky  ][kx+1], acc[j][1]);
                        acc[j][2] = fma2(w, pp[ky+1][kx  ], acc[j][2]);
                        acc[j][3] = fma2(w, pp[ky+1][kx+1], acc[j][3]);
                    }
            }
        }
#pragma unroll
        for (int j = 0; j < 4; j++) {
            float2 a0 = unpack2(acc[j][0]), a1v = unpack2(acc[j][1]);
            float2 a2v = unpack2(acc[j][2]), a3 = unpack2(acc[j][3]);
            int co = cg*8 + 2*j;
            float va = fmaxf(fmaxf(a0.x, a1v.x), fmaxf(a2v.x, a3.x)) + sb[co];
            float vb = fmaxf(fmaxf(a0.y, a1v.y), fmaxf(a2v.y, a3.y)) + sb[co+1];
            g_a1[(size_t)n*A1_PER + co*225 + pos]     = fmaxf(va, 0.f);
            g_a1[(size_t)n*A1_PER + (co+1)*225 + pos] = fmaxf(vb, 0.f);
        }
    }
}

// ---------------- stats0 + absorbed weight repack (blocks 0..47) ----------------
__global__ void __launch_bounds__(256) k_stats0(const float* __restrict__ cb,
                                                const float* __restrict__ w2,
                                                const float* __restrict__ w3) {
    int n = blockIdx.x, tid = threadIdx.x;
    int t = n * 256 + tid;
    if (t < KCB) {
        float s = 0.f;
#pragma unroll
        for (int c = 0; c < 32; c++) { float v = cb[t*32+c]; s = fmaf(v, v, s); }
        g_cbsq[t] = s;
    }
    if (t < 10240) {                      // conv2 co-pairs [ci][cp][10]
        int k = t % 10, r = t / 10, ci = r / 16, cp = r % 16;
        float a = 0.f, b = 0.f;
        if (k < 9) { a = w2[(2*cp)*576 + ci*9 + k]; b = w2[(2*cp+1)*576 + ci*9 + k]; }
        g_w2p[t] = make_float2(a, b);
    }
    if (t < 5120) {                       // conv3 co-pairs [ci][cp][10]
        int k = t % 10, r = t / 10, ci = r / 16, cp = r % 16;
        float a = 0.f, b = 0.f;
        if (k < 9) { a = w3[(2*cp)*288 + ci*9 + k]; b = w3[(2*cp+1)*288 + ci*9 + k]; }
        g_w3p2[t] = make_float2(a, b);
    }

    int warp = tid >> 5, lane = tid & 31;
    const float* base = g_a1 + (size_t)n*A1_PER + warp*8*225;
    float s[8], q[8];
#pragma unroll
    for (int c = 0; c < 8; c++) { s[c] = 0.f; q[c] = 0.f; }
#pragma unroll
    for (int c = 0; c < 8; c++) {
        const float* p = base + c*225;
        for (int i = lane; i < 225; i += 32) {
            float v = p[i]; s[c] += v; q[c] = fmaf(v, v, q[c]);
        }
    }
#pragma unroll
    for (int c = 0; c < 8; c++) {
        float a = wredsum(s[c]);
        float b = wredsum(q[c]);
        if (lane == 0) {
            atomicAdd(g_sum1 + warp*8 + c, a);
            atomicAdd(g_ssq1 + warp*8 + c, b);
        }
    }
}

// ---------------- conv2 v11: v10 + cog-uniform warp remap ----------------
#define C2P 22
__global__ void __launch_bounds__(576, 2) k_conv2(const float* __restrict__ c2b,
                                                  const float* __restrict__ bn1s,
                                                  const float* __restrict__ bn1b) {
    __shared__ __align__(16) float  sin[2*16*15*C2P];   // [s][ci][y:15][x pitch22]
    __shared__ __align__(16) float2 swp[16*16*10];      // [ci][cp][10]
    __shared__ float sg1[64], sb1[64];
    __shared__ float ssum[32], sssq[32];
    int n0 = blockIdx.x * 2, tid = threadIdx.x;
    // cog-major mapping: ~half the warps are cog-pure -> broadcast weight loads
    int cog = tid / 72, q = tid % 72;
    int s = q / 36, pg = q % 36;
    int y0 = (pg / 6) * 2, x0 = (pg % 6) * 2;

    if (tid < 64) {
        float m  = g_sum1[tid] * (1.f / 460800.f);
        float vv = fmaxf(g_ssq1[tid] * (1.f / 460800.f) - m*m, 0.f);
        float gg = bn1s[tid] * rsqrtf(vv + BN_EPS);
        sg1[tid] = gg; sb1[tid] = bn1b[tid] - m * gg;
    }
    if (tid < 32) { ssum[tid] = 0.f; sssq[tid] = 0.f; }

    int st_ss = tid / 240, st_rem = tid % 240, st_ci = st_rem / 15, st_xx = st_rem % 15;

    u64 acc[2][4];
#pragma unroll
    for (int j = 0; j < 2; j++)
#pragma unroll
        for (int p = 0; p < 4; p++) acc[j][p] = 0ull;

    for (int ch = 0; ch < 4; ch++) {
        __syncthreads();
        if (tid < 480) {
            int c = ch*16 + st_ci;
            const float* src = g_a1 + (size_t)(n0+st_ss)*A1_PER + c*225 + st_xx;
            float* dst = sin + (st_ss*16 + st_ci)*330 + st_xx;
            float gg = sg1[c], bb = sb1[c];
#pragma unroll
            for (int y = 0; y < 15; y++)
                dst[y*C2P] = fmaf(src[y*15], gg, bb);
        }
        {
            const float4* wsrc = (const float4*)(g_w2p + (size_t)ch*2560);
            float4* wdst = (float4*)swp;
            for (int i = tid; i < 1280; i += 576) wdst[i] = wsrc[i];
        }
        __syncthreads();

        const float* sp = sin + s*16*330 + y0*C2P + x0;
#pragma unroll 2
        for (int ci = 0; ci < 16; ci++) {
            u64 pp[4][4];
#pragma unroll
            for (int rr = 0; rr < 4; rr++) {
                float2 f01 = *(const float2*)(sp + ci*330 + rr*C2P);
                float2 f23 = *(const float2*)(sp + ci*330 + rr*C2P + 2);
                pp[rr][0] = dup2(f01.x); pp[rr][1] = dup2(f01.y);
                pp[rr][2] = dup2(f23.x); pp[rr][3] = dup2(f23.y);
            }
            const ulonglong2* wv = (const ulonglong2*)(swp + (ci*16 + cog*2)*10);
#pragma unroll
            for (int j = 0; j < 2; j++) {
                ulonglong2 wa = wv[j*5+0], wb = wv[j*5+1], wc = wv[j*5+2],
                           wd = wv[j*5+3], we = wv[j*5+4];
                u64 wk[9] = {wa.x, wa.y, wb.x, wb.y, wc.x, wc.y, wd.x, wd.y, we.x};
#pragma unroll
                for (int ky = 0; ky < 3; ky++)
#pragma unroll
                    for (int kx = 0; kx < 3; kx++) {
                        u64 w = wk[ky*3+kx];
                        acc[j][0] = fma2(w, pp[ky  ][kx  ], acc[j][0]);
                        acc[j][1] = fma2(w, pp[ky  ][kx+1], acc[j][1]);
                        acc[j][2] = fma2(w, pp[ky+1][kx  ], acc[j][2]);
                        acc[j][3] = fma2(w, pp[ky+1][kx+1], acc[j][3]);
                    }
            }
        }
    }

#pragma unroll
    for (int j = 0; j < 2; j++) {
        float2 a0 = unpack2(acc[j][0]), a1v = unpack2(acc[j][1]);
        float2 a2v = unpack2(acc[j][2]), a3 = unpack2(acc[j][3]);
        int co = cog*4 + 2*j;
        float va = fmaxf(fmaxf(a0.x, a1v.x), fmaxf(a2v.x, a3.x)) + __ldg(c2b + co);
        float vb = fmaxf(fmaxf(a0.y, a1v.y), fmaxf(a2v.y, a3.y)) + __ldg(c2b + co + 1);
        va = fmaxf(va, 0.f); vb = fmaxf(vb, 0.f);
        *(float2*)(g_a2 + ((size_t)(n0+s)*36 + pg)*32 + co) = make_float2(va, vb);
        atomicAdd(&ssum[co],   va); atomicAdd(&sssq[co],   va*va);
        atomicAdd(&ssum[co+1], vb); atomicAdd(&sssq[co+1], vb*vb);
    }
    __syncthreads();
    if (tid < 32) {
        atomicAdd(g_sum2 + tid, ssum[tid]);
        atomicAdd(g_ssq2 + tid, sssq[tid]);
    }
}

// ---------------- conv3 v2: f32x2 co-pairs ----------------
// smem: sw3p 10240 f (5120 f2), sin2 4752 f, stats/coefs 128 f
#define C3_SW   0
#define C3_SIN  10240
#define C3_ST   14992
#define CONV3_SMEM (15120 * 4)
__global__ void __launch_bounds__(256) k_conv3(const float* __restrict__ bias,
                                               const float* __restrict__ bn2s,
                                               const float* __restrict__ bn2b) {
    extern __shared__ __align__(16) float sm3[];
    float2* sw3p = (float2*)(sm3 + C3_SW);
    float* sin2 = sm3 + C3_SIN;
    float* ssum = sm3 + C3_ST;
    float* sssq = sm3 + C3_ST + 32;
    float* sg2  = sm3 + C3_ST + 64;
    float* sb2c = sm3 + C3_ST + 96;
    int n0 = blockIdx.x * 4, tid = threadIdx.x;

    if (tid < 32) {
        float m  = g_sum2[tid] * (1.f / 73728.f);
        float vv = fmaxf(g_ssq2[tid] * (1.f / 73728.f) - m*m, 0.f);
        float gg = bn2s[tid] * rsqrtf(vv + BN_EPS);
        sg2[tid] = gg; sb2c[tid] = bn2b[tid] - m * gg;
        ssum[tid] = 0.f; sssq[tid] = 0.f;
    }
    __syncthreads();

    {
        const float4* wsrc = (const float4*)g_w3p2;
        float4* wdst = (float4*)sw3p;
        for (int i = tid; i < 2560; i += 256) wdst[i] = wsrc[i];
    }
    for (int i = tid; i < 4608; i += 256) {
        int s = i / 1152, j = i % 1152, pos = j / 32, c = j & 31;
        sin2[s*1188 + pos*33 + c] = fmaf(g_a2[(size_t)(n0+s)*A2_PER + j], sg2[c], sb2c[c]);
    }
    __syncthreads();

    int s = tid / 64, r = tid % 64, pos = r % 16, grp = r / 16;   // grp: 4 co-pairs
    int py = pos / 4, px = pos % 4;
    u64 acc[4];
#pragma unroll
    for (int a = 0; a < 4; a++) acc[a] = 0ull;

    const float* sb2 = sin2 + s*1188;
    for (int ci = 0; ci < 32; ci++) {
        u64 pp[9];
#pragma unroll
        for (int ky = 0; ky < 3; ky++)
#pragma unroll
            for (int kx = 0; kx < 3; kx++)
                pp[ky*3+kx] = dup2(sb2[((py+ky)*6 + px+kx)*33 + ci]);
        const ulonglong2* wv = (const ulonglong2*)(sw3p + (ci*16 + grp*4)*10);
#pragma unroll
        for (int j = 0; j < 4; j++) {
            ulonglong2 wa = wv[j*5+0], wb = wv[j*5+1], wc = wv[j*5+2],
                       wd = wv[j*5+3], we = wv[j*5+4];
            u64 wk[9] = {wa.x, wa.y, wb.x, wb.y, wc.x, wc.y, wd.x, wd.y, we.x};
            u64 a = acc[j];
#pragma unroll
            for (int k = 0; k < 9; k++) a = fma2(wk[k], pp[k], a);
            acc[j] = a;
        }
    }
#pragma unroll
    for (int j = 0; j < 4; j++) {
        float2 v2 = unpack2(acc[j]);
        int co = grp*8 + 2*j;
        float va = fmaxf(v2.x + bias[co],   0.f);
        float vb = fmaxf(v2.y + bias[co+1], 0.f);
        g_hp[(size_t)(n0+s)*H_PER + co*16 + pos]     = va;
        g_hp[(size_t)(n0+s)*H_PER + (co+1)*16 + pos] = vb;
        atomicAdd(&ssum[co],   va); atomicAdd(&sssq[co],   va*va);
        atomicAdd(&ssum[co+1], vb); atomicAdd(&sssq[co+1], vb*vb);
    }
    __syncthreads();
    if (tid < 32) {
        atomicAdd(g_sum3 + tid, ssum[tid]);
        atomicAdd(g_ssq3 + tid, sssq[tid]);
    }
}

// ---------------- vqfc v3 (proven) ----------------
__global__ void __launch_bounds__(256) k_vqfc(const float* __restrict__ cb,
                                              const float* __restrict__ fc1w,
                                              const float* __restrict__ fc1b,
                                              const float* __restrict__ fc2w,
                                              const float* __restrict__ fc2b,
                                              const float* __restrict__ bn3s,
                                              const float* __restrict__ bn3b,
                                              float* __restrict__ out) {
    __shared__ float scb[KCB*32];
    __shared__ float scbT[32*104];
    __shared__ float scbsq[104];
    __shared__ float hs[1024];
    __shared__ float bl[1024];
    __shared__ float z1[128];
    __shared__ float z1h[256];
    __shared__ int   idxs[32];
    __shared__ float wred[8];
    __shared__ float sg3[32], sb3c[32];
    int n0 = blockIdx.x * 2, tid = threadIdx.x;
    unsigned full = 0xffffffffu;

    if (tid < 32) {
        float m  = g_sum3[tid] * (1.f / 32768.f);
        float vv = fmaxf(g_ssq3[tid] * (1.f / 32768.f) - m*m, 0.f);
        float gg = bn3s[tid] * rsqrtf(vv + BN_EPS);
        sg3[tid] = gg; sb3c[tid] = bn3b[tid] - m * gg;
    }
    __syncthreads();

    for (int i = tid; i < KCB*32; i += 256) {
        float v = cb[i];
        scb[i] = v;
        scbT[(i & 31)*104 + (i >> 5)] = v;
    }
    if (tid < KCB) scbsq[tid] = g_cbsq[tid];
    for (int i = tid; i < 1024; i += 256) {
        int s = i >> 9, j = i & 511, c = j >> 4;
        float v = fmaf(g_hp[(size_t)(n0+s)*H_PER + j], sg3[c], sb3c[c]);
        hs[i] = v;
        out[H_OFF + (size_t)(n0+s)*512 + j] = v;
    }
    __syncthreads();

    {
        int s = tid >> 7, r = tid & 127, pos = r >> 3, sub = r & 7;
        float z[32];
#pragma unroll
        for (int c = 0; c < 32; c++) z[c] = hs[s*512 + c*16 + pos];
        float zz = 0.f;
#pragma unroll
        for (int c = 0; c < 32; c++) zz = fmaf(z[c], z[c], zz);
        float bd = INFINITY; int bi = 0;
        for (int k = sub; k < KCB; k += 8) {
            float dot = 0.f;
#pragma unroll
            for (int c = 0; c < 32; c++) dot = fmaf(scbT[c*104 + k], z[c], dot);
            float d = zz + scbsq[k] - 2.f*dot;
            if (d < bd) { bd = d; bi = k; }
        }
#pragma unroll
        for (int off = 4; off; off >>= 1) {
            float od = __shfl_down_sync(full, bd, off, 8);
            int   oi = __shfl_down_sync(full, bi, off, 8);
            if (od < bd || (od == bd && oi < bi)) { bd = od; bi = oi; }
        }
        if (sub == 0) idxs[s*16 + pos] = bi;
    }
    __syncthreads();

    float vqs = 0.f;
    for (int i = tid; i < 1024; i += 256) {
        int s = i >> 9, j = i & 511, c = j >> 4, p2 = j & 15;
        float q = scb[idxs[s*16 + p2]*32 + c];
        float zv = hs[i];
        float df = q - zv;
        vqs = fmaf(df, df, vqs);
        out[RECON_OFF + (size_t)(n0+s)*512 + j] = q;
        bl[i] = fmaf(0.5f, q, zv);
    }
    vqs = wredsum(vqs);
    if ((tid & 31) == 0) wred[tid >> 5] = vqs;
    __syncthreads();
    if (tid == 0) {
        float a = 0.f;
#pragma unroll
        for (int w = 0; w < 8; w++) a += wred[w];
        atomicAdd(&g_vq, a);
    }

    {
        int o = tid & 63, hh = (tid >> 6) & 1, ss = tid >> 7;
        const float4* wp4 = (const float4*)(fc1w + o*512 + hh*256);
        const float4* bl4 = (const float4*)(bl + ss*512 + hh*256);
        float a = 0.f;
#pragma unroll 8
        for (int t = 0; t < 64; t++) {
            float4 w = wp4[t], b = bl4[t];
            a = fmaf(w.x, b.x, a); a = fmaf(w.y, b.y, a);
            a = fmaf(w.z, b.z, a); a = fmaf(w.w, b.w, a);
        }
        z1h[tid] = a;
    }
    __syncthreads();
    if (tid < 128) {
        int ss = tid >> 6, o = tid & 63;
        z1[ss*64 + o] = fmaxf(z1h[ss*128 + o] + z1h[ss*128 + 64 + o] + fc1b[o], 0.f);
    }
    __syncthreads();

    if (tid < 64) {
        int s = tid >> 5, lane = tid & 31;
        float y = -INFINITY;
        if (lane < 10) {
            const float* wp = fc2w + lane*64;
            float a = 0.f;
#pragma unroll
            for (int j = 0; j < 64; j++) a = fmaf(wp[j], z1[s*64 + j], a);
            y = a + fc2b[lane];
        }
        float m = y;
#pragma unroll
        for (int off = 16; off; off >>= 1) m = fmaxf(m, __shfl_xor_sync(full, m, off));
        float e = (lane < 10) ? expf(y - m) : 0.f;
        float ssum = e;
#pragma unroll
        for (int off = 16; off; off >>= 1) ssum += __shfl_xor_sync(full, ssum, off);
        if (lane < 10) out[LP_OFF + (size_t)(n0+s)*10 + lane] = y - m - logf(ssum);
    }
}

__global__ void k_final(float* __restrict__ out) {
    out[LOSS_OFF] = 1.25f * g_vq / (float)(B * 16 * 32);
}

// ---------------- launch ----------------
extern "C" void kernel_launch(void* const* d_in, const int* in_sizes, int n_in,
                              void* d_out, int out_size) {
    const float* x      = (const float*)d_in[0];
    const float* c1w    = (const float*)d_in[1];
    const float* c1b    = (const float*)d_in[2];
    const float* bn1s   = (const float*)d_in[3];
    const float* bn1b   = (const float*)d_in[4];
    const float* c2w    = (const float*)d_in[5];
    const float* c2b    = (const float*)d_in[6];
    const float* bn2s   = (const float*)d_in[7];
    const float* bn2b   = (const float*)d_in[8];
    const float* c3w    = (const float*)d_in[9];
    const float* c3b    = (const float*)d_in[10];
    const float* bn3s   = (const float*)d_in[11];
    const float* bn3b   = (const float*)d_in[12];
    const float* cb     = (const float*)d_in[13];
    const float* fc1w   = (const float*)d_in[14];
    const float* fc1b   = (const float*)d_in[15];
    const float* fc2w   = (const float*)d_in[16];
    const float* fc2b   = (const float*)d_in[17];
    float* out = (float*)d_out;

    cudaFuncSetAttribute(k_conv3, cudaFuncAttributeMaxDynamicSharedMemorySize, CONV3_SMEM);

    k_conv1<<<B, 256>>>(x, c1w, c1b);                              // 0 (self-repack + stat zero)
    k_stats0<<<B, 256>>>(cb, c2w, c3w);                            // 1 (+ weight repack)
    k_conv2<<<B/2, 576>>>(c2b, bn1s, bn1b);                        // 2
    k_conv3<<<B/4, 256, CONV3_SMEM>>>(c3b, bn2s, bn2b);            // 3  <- ncu capture
    k_vqfc<<<B/2, 256>>>(cb, fc1w, fc1b, fc2w, fc2b, bn3s, bn3b, out); // 4
    k_final<<<1, 1>>>(out);                                        // 5
}

// round 15
// speedup vs baseline: 1.3113x; 1.3113x over previous
#include <cuda_runtime.h>
#include <math.h>

#define B 2048
#define A1_PER (64*225)       // 14400
#define A2_PER (32*36)        // 1152
#define H_PER 512
#define KCB 100
#define BN_EPS 1e-5f

#define RECON_OFF 0
#define H_OFF     (B*H_PER)
#define LOSS_OFF  (2*B*H_PER)
#define LP_OFF    (2*B*H_PER + 1)

typedef unsigned long long u64;

// ---------------- device scratch ----------------
__device__ __align__(16) float g_a1[B*A1_PER];    // conv1 out [n][co][225] (pre-BN)
__device__ __align__(16) float g_a2[B*A2_PER];    // conv2 out [n][pos36][co32]
__device__ __align__(16) float g_hp[B*H_PER];     // conv3 out [n][co][16]
__device__ __align__(16) float2 g_w2p[64*16*10];  // conv2 co-pairs [ci][cp][10]
__device__ __align__(16) float  g_w3p[32*32*12];  // conv3 [ci][co][12]
__device__ float g_sum1[64], g_ssq1[64];
__device__ float g_sum2[32], g_ssq2[32];
__device__ float g_sum3[32], g_ssq3[32];
__device__ float g_cbsq[KCB];
__device__ float g_vq;

__device__ __forceinline__ float wredsum(float v) {
#pragma unroll
    for (int o = 16; o; o >>= 1) v += __shfl_down_sync(0xffffffffu, v, o);
    return v;
}
__device__ __forceinline__ u64 pack2(float x, float y) {
    u64 r; asm("mov.b64 %0, {%1,%2};" : "=l"(r) : "f"(x), "f"(y)); return r;
}
__device__ __forceinline__ u64 dup2(float x) { return pack2(x, x); }
__device__ __forceinline__ u64 fma2(u64 a, u64 b, u64 c) {
    u64 d; asm("fma.rn.f32x2 %0, %1, %2, %3;" : "=l"(d) : "l"(a), "l"(b), "l"(c)); return d;
}
__device__ __forceinline__ float2 unpack2(u64 a) {
    float2 f; asm("mov.b64 {%0,%1}, %2;" : "=f"(f.x), "=f"(f.y) : "l"(a)); return f;
}

// ---------------- conv1 (r13 math, self-repack + stat zero) ----------------
__global__ void __launch_bounds__(256, 3) k_conv1(const float* __restrict__ x,
                                                  const float* __restrict__ w1raw,
                                                  const float* __restrict__ bias) {
    __shared__ __align__(16) float  sx[3*32*34];
    __shared__ __align__(16) float2 swp1[3*32*10];    // co-pairs [ci][cp32][10]
    __shared__ float sb[64];
    int n = blockIdx.x, tid = threadIdx.x;

    if (n == 0) {
        if (tid < 64) { g_sum1[tid] = 0.f; g_ssq1[tid] = 0.f; }
        if (tid < 32) { g_sum2[tid] = 0.f; g_ssq2[tid] = 0.f;
                        g_sum3[tid] = 0.f; g_ssq3[tid] = 0.f; }
        if (tid == 0) g_vq = 0.f;
    }

    const float4* x4 = (const float4*)(x + (size_t)n * 3072);
    for (int i = tid; i < 768; i += 256) {
        float4 v = x4[i];
        int e = i * 4, ci = e >> 10, rem = e & 1023, y = rem >> 5, xc = rem & 31;
        float* d = sx + ci*1088 + y*34 + xc;
        d[0] = v.x; d[1] = v.y; d[2] = v.z; d[3] = v.w;
    }
    for (int i = tid; i < 960; i += 256) {
        int k = i % 10, r = i / 10, ci = r / 32, cp = r % 32;
        float a = 0.f, b = 0.f;
        if (k < 9) { a = w1raw[(2*cp)*27 + ci*9 + k]; b = w1raw[(2*cp+1)*27 + ci*9 + k]; }
        swp1[i] = make_float2(a, b);
    }
    if (tid < 64) sb[tid] = bias[tid];
    __syncthreads();

    for (int it = tid; it < 1800; it += 256) {
        int pos = it % 225, cg = it / 225;
        int py2 = (pos / 15) * 2, px2 = (pos % 15) * 2;
        u64 acc[4][4];
#pragma unroll
        for (int j = 0; j < 4; j++)
#pragma unroll
            for (int p = 0; p < 4; p++) acc[j][p] = 0ull;

#pragma unroll
        for (int ci = 0; ci < 3; ci++) {
            const float* sp = sx + ci*1088 + py2*34 + px2;
            u64 pp[4][4];
#pragma unroll
            for (int rr = 0; rr < 4; rr++) {
                float2 f01 = *(const float2*)(sp + rr*34);
                float2 f23 = *(const float2*)(sp + rr*34 + 2);
                pp[rr][0] = dup2(f01.x); pp[rr][1] = dup2(f01.y);
                pp[rr][2] = dup2(f23.x); pp[rr][3] = dup2(f23.y);
            }
            const ulonglong2* wv = (const ulonglong2*)(swp1 + (ci*32 + cg*4)*10);
#pragma unroll
            for (int j = 0; j < 4; j++) {
                ulonglong2 wa = wv[j*5+0], wb = wv[j*5+1], wc = wv[j*5+2],
                           wd = wv[j*5+3], we = wv[j*5+4];
                u64 wk[9] = {wa.x, wa.y, wb.x, wb.y, wc.x, wc.y, wd.x, wd.y, we.x};
#pragma unroll
                for (int ky = 0; ky < 3; ky++)
#pragma unroll
                    for (int kx = 0; kx < 3; kx++) {
                        u64 w = wk[ky*3+kx];
                        acc[j][0] = fma2(w, pp[ky  ][kx  ], acc[j][0]);
                        acc[j][1] = fma2(w, pp[ky  ][kx+1], acc[j][1]);
                        acc[j][2] = fma2(w, pp[ky+1][kx  ], acc[j][2]);
                        acc[j][3] = fma2(w, pp[ky+1][kx+1], acc[j][3]);
                    }
            }
        }
#pragma unroll
        for (int j = 0; j < 4; j++) {
            float2 a0 = unpack2(acc[j][0]), a1v = unpack2(acc[j][1]);
            float2 a2v = unpack2(acc[j][2]), a3 = unpack2(acc[j][3]);
            int co = cg*8 + 2*j;
            float va = fmaxf(fmaxf(a0.x, a1v.x), fmaxf(a2v.x, a3.x)) + sb[co];
            float vb = fmaxf(fmaxf(a0.y, a1v.y), fmaxf(a2v.y, a3.y)) + sb[co+1];
            g_a1[(size_t)n*A1_PER + co*225 + pos]     = fmaxf(va, 0.f);
            g_a1[(size_t)n*A1_PER + (co+1)*225 + pos] = fmaxf(vb, 0.f);
        }
    }
}

// ---------------- stats0 + absorbed weight repack ----------------
__global__ void __launch_bounds__(256) k_stats0(const float* __restrict__ cb,
                                                const float* __restrict__ w2,
                                                const float* __restrict__ w3) {
    int n = blockIdx.x, tid = threadIdx.x;
    int t = n * 256 + tid;
    if (t < KCB) {
        float s = 0.f;
#pragma unroll
        for (int c = 0; c < 32; c++) { float v = cb[t*32+c]; s = fmaf(v, v, s); }
        g_cbsq[t] = s;
    }
    if (t < 10240) {                      // conv2 co-pairs [ci][cp][10]
        int k = t % 10, r = t / 10, ci = r / 16, cp = r % 16;
        float a = 0.f, b = 0.f;
        if (k < 9) { a = w2[(2*cp)*576 + ci*9 + k]; b = w2[(2*cp+1)*576 + ci*9 + k]; }
        g_w2p[t] = make_float2(a, b);
    }
    if (t < 12288) {                      // conv3 [ci][co][12] (r13 layout)
        int k = t % 12, r = t / 12, ci = r / 32, co = r % 32;
        g_w3p[t] = (k < 9) ? w3[co*288 + ci*9 + k] : 0.f;
    }

    int warp = tid >> 5, lane = tid & 31;
    const float* base = g_a1 + (size_t)n*A1_PER + warp*8*225;
    float s[8], q[8];
#pragma unroll
    for (int c = 0; c < 8; c++) { s[c] = 0.f; q[c] = 0.f; }
#pragma unroll
    for (int c = 0; c < 8; c++) {
        const float* p = base + c*225;
        for (int i = lane; i < 225; i += 32) {
            float v = p[i]; s[c] += v; q[c] = fmaf(v, v, q[c]);
        }
    }
#pragma unroll
    for (int c = 0; c < 8; c++) {
        float a = wredsum(s[c]);
        float b = wredsum(q[c]);
        if (lane == 0) {
            atomicAdd(g_sum1 + warp*8 + c, a);
            atomicAdd(g_ssq1 + warp*8 + c, b);
        }
    }
}

// ---------------- conv2 v10 (r13 verbatim, proven 285.8us) ----------------
#define C2P 22
__global__ void __launch_bounds__(576, 2) k_conv2(const float* __restrict__ c2b,
                                                  const float* __restrict__ bn1s,
                                                  const float* __restrict__ bn1b) {
    __shared__ __align__(16) float  sin[2*16*15*C2P];
    __shared__ __align__(16) float2 swp[16*16*10];
    __shared__ float sg1[64], sb1[64];
    __shared__ float ssum[32], sssq[32];
    int n0 = blockIdx.x * 2, tid = threadIdx.x;
    int s = tid / 288, r = tid % 288, pg = r % 36, cog = r / 36;
    int y0 = (pg / 6) * 2, x0 = (pg % 6) * 2;

    if (tid < 64) {
        float m  = g_sum1[tid] * (1.f / 460800.f);
        float vv = fmaxf(g_ssq1[tid] * (1.f / 460800.f) - m*m, 0.f);
        float gg = bn1s[tid] * rsqrtf(vv + BN_EPS);
        sg1[tid] = gg; sb1[tid] = bn1b[tid] - m * gg;
    }
    if (tid < 32) { ssum[tid] = 0.f; sssq[tid] = 0.f; }

    int st_ss = tid / 240, st_rem = tid % 240, st_ci = st_rem / 15, st_xx = st_rem % 15;

    u64 acc[2][4];
#pragma unroll
    for (int j = 0; j < 2; j++)
#pragma unroll
        for (int p = 0; p < 4; p++) acc[j][p] = 0ull;

    for (int ch = 0; ch < 4; ch++) {
        __syncthreads();
        if (tid < 480) {
            int c = ch*16 + st_ci;
            const float* src = g_a1 + (size_t)(n0+st_ss)*A1_PER + c*225 + st_xx;
            float* dst = sin + (st_ss*16 + st_ci)*330 + st_xx;
            float gg = sg1[c], bb = sb1[c];
#pragma unroll
            for (int y = 0; y < 15; y++)
                dst[y*C2P] = fmaf(src[y*15], gg, bb);
        }
        {
            const float4* wsrc = (const float4*)(g_w2p + (size_t)ch*2560);
            float4* wdst = (float4*)swp;
            for (int i = tid; i < 1280; i += 576) wdst[i] = wsrc[i];
        }
        __syncthreads();

        const float* sp = sin + s*16*330 + y0*C2P + x0;
#pragma unroll 2
        for (int ci = 0; ci < 16; ci++) {
            u64 pp[4][4];
#pragma unroll
            for (int rr = 0; rr < 4; rr++) {
                float2 f01 = *(const float2*)(sp + ci*330 + rr*C2P);
                float2 f23 = *(const float2*)(sp + ci*330 + rr*C2P + 2);
                pp[rr][0] = dup2(f01.x); pp[rr][1] = dup2(f01.y);
                pp[rr][2] = dup2(f23.x); pp[rr][3] = dup2(f23.y);
            }
            const ulonglong2* wv = (const ulonglong2*)(swp + (ci*16 + cog*2)*10);
#pragma unroll
            for (int j = 0; j < 2; j++) {
                ulonglong2 wa = wv[j*5+0], wb = wv[j*5+1], wc = wv[j*5+2],
                           wd = wv[j*5+3], we = wv[j*5+4];
                u64 wk[9] = {wa.x, wa.y, wb.x, wb.y, wc.x, wc.y, wd.x, wd.y, we.x};
#pragma unroll
                for (int ky = 0; ky < 3; ky++)
#pragma unroll
                    for (int kx = 0; kx < 3; kx++) {
                        u64 w = wk[ky*3+kx];
                        acc[j][0] = fma2(w, pp[ky  ][kx  ], acc[j][0]);
                        acc[j][1] = fma2(w, pp[ky  ][kx+1], acc[j][1]);
                        acc[j][2] = fma2(w, pp[ky+1][kx  ], acc[j][2]);
                        acc[j][3] = fma2(w, pp[ky+1][kx+1], acc[j][3]);
                    }
            }
        }
    }

#pragma unroll
    for (int j = 0; j < 2; j++) {
        float2 a0 = unpack2(acc[j][0]), a1v = unpack2(acc[j][1]);
        float2 a2v = unpack2(acc[j][2]), a3 = unpack2(acc[j][3]);
        int co = cog*4 + 2*j;
        float va = fmaxf(fmaxf(a0.x, a1v.x), fmaxf(a2v.x, a3.x)) + __ldg(c2b + co);
        float vb = fmaxf(fmaxf(a0.y, a1v.y), fmaxf(a2v.y, a3.y)) + __ldg(c2b + co + 1);
        va = fmaxf(va, 0.f); vb = fmaxf(vb, 0.f);
        *(float2*)(g_a2 + ((size_t)(n0+s)*36 + pg)*32 + co) = make_float2(va, vb);
        atomicAdd(&ssum[co],   va); atomicAdd(&sssq[co],   va*va);
        atomicAdd(&ssum[co+1], vb); atomicAdd(&sssq[co+1], vb*vb);
    }
    __syncthreads();
    if (tid < 32) {
        atomicAdd(g_sum2 + tid, ssum[tid]);
        atomicAdd(g_ssq2 + tid, sssq[tid]);
    }
}

// ---------------- conv3 (r13 verbatim) ----------------
#define C3_SW   0
#define C3_SIN  12288
#define C3_ST   17040
#define C3_CF   17104
#define CONV3_SMEM (17168 * 4)
__global__ void __launch_bounds__(256) k_conv3(const float* __restrict__ bias,
                                               const float* __restrict__ bn2s,
                                               const float* __restrict__ bn2b) {
    extern __shared__ __align__(16) float sm3[];
    float* sw3  = sm3 + C3_SW;
    float* sin2 = sm3 + C3_SIN;
    float* ssum = sm3 + C3_ST;
    float* sssq = sm3 + C3_ST + 32;
    float* sg2  = sm3 + C3_CF;
    float* sb2c = sm3 + C3_CF + 32;
    int n0 = blockIdx.x * 4, tid = threadIdx.x;

    if (tid < 32) {
        float m  = g_sum2[tid] * (1.f / 73728.f);
        float vv = fmaxf(g_ssq2[tid] * (1.f / 73728.f) - m*m, 0.f);
        float gg = bn2s[tid] * rsqrtf(vv + BN_EPS);
        sg2[tid] = gg; sb2c[tid] = bn2b[tid] - m * gg;
        ssum[tid] = 0.f; sssq[tid] = 0.f;
    }
    __syncthreads();

    {
        const float4* wsrc = (const float4*)g_w3p;
        float4* wdst = (float4*)sw3;
        for (int i = tid; i < 3072; i += 256) wdst[i] = wsrc[i];
    }
    for (int i = tid; i < 4608; i += 256) {
        int s = i / 1152, j = i % 1152, pos = j / 32, c = j & 31;
        sin2[s*1188 + pos*33 + c] = fmaf(g_a2[(size_t)(n0+s)*A2_PER + j], sg2[c], sb2c[c]);
    }
    __syncthreads();

    int s = tid / 64, r = tid % 64, pos = r % 16, grp = r / 16;
    int py = pos / 4, px = pos % 4;
    float acc[8];
#pragma unroll
    for (int a = 0; a < 8; a++) acc[a] = 0.f;

    const float* sb2 = sin2 + s*1188;
    for (int ci = 0; ci < 32; ci++) {
        float p[9];
#pragma unroll
        for (int ky = 0; ky < 3; ky++)
#pragma unroll
            for (int kx = 0; kx < 3; kx++) p[ky*3+kx] = sb2[((py+ky)*6 + px+kx)*33 + ci];
        const float* wb = sw3 + (ci*32 + grp*8)*12;
#pragma unroll
        for (int cl = 0; cl < 8; cl++) {
            const float4* w4 = (const float4*)(wb + cl*12);
            float4 wa = w4[0], wc = w4[1];
            float wv[9] = {wa.x, wa.y, wa.z, wa.w, wc.x, wc.y, wc.z, wc.w, wb[cl*12+8]};
            float a = acc[cl];
#pragma unroll
            for (int k = 0; k < 9; k++) a = fmaf(wv[k], p[k], a);
            acc[cl] = a;
        }
    }
#pragma unroll
    for (int cl = 0; cl < 8; cl++) {
        int co = grp*8 + cl;
        float v = fmaxf(acc[cl] + bias[co], 0.f);
        g_hp[(size_t)(n0+s)*H_PER + co*16 + pos] = v;
        atomicAdd(&ssum[co], v);
        atomicAdd(&sssq[co], v*v);
    }
    __syncthreads();
    if (tid < 32) {
        atomicAdd(g_sum3 + tid, ssum[tid]);
        atomicAdd(g_ssq3 + tid, sssq[tid]);
    }
}

// ---------------- vqfc v3 (r13 verbatim) ----------------
__global__ void __launch_bounds__(256) k_vqfc(const float* __restrict__ cb,
                                              const float* __restrict__ fc1w,
                                              const float* __restrict__ fc1b,
                                              const float* __restrict__ fc2w,
                                              const float* __restrict__ fc2b,
                                              const float* __restrict__ bn3s,
                                              const float* __restrict__ bn3b,
                                              float* __restrict__ out) {
    __shared__ float scb[KCB*32];
    __shared__ float scbT[32*104];
    __shared__ float scbsq[104];
    __shared__ float hs[1024];
    __shared__ float bl[1024];
    __shared__ float z1[128];
    __shared__ float z1h[256];
    __shared__ int   idxs[32];
    __shared__ float wred[8];
    __shared__ float sg3[32], sb3c[32];
    int n0 = blockIdx.x * 2, tid = threadIdx.x;
    unsigned full = 0xffffffffu;

    if (tid < 32) {
        float m  = g_sum3[tid] * (1.f / 32768.f);
        float vv = fmaxf(g_ssq3[tid] * (1.f / 32768.f) - m*m, 0.f);
        float gg = bn3s[tid] * rsqrtf(vv + BN_EPS);
        sg3[tid] = gg; sb3c[tid] = bn3b[tid] - m * gg;
    }
    __syncthreads();

    for (int i = tid; i < KCB*32; i += 256) {
        float v = cb[i];
        scb[i] = v;
        scbT[(i & 31)*104 + (i >> 5)] = v;
    }
    if (tid < KCB) scbsq[tid] = g_cbsq[tid];
    for (int i = tid; i < 1024; i += 256) {
        int s = i >> 9, j = i & 511, c = j >> 4;
        float v = fmaf(g_hp[(size_t)(n0+s)*H_PER + j], sg3[c], sb3c[c]);
        hs[i] = v;
        out[H_OFF + (size_t)(n0+s)*512 + j] = v;
    }
    __syncthreads();

    {
        int s = tid >> 7, r = tid & 127, pos = r >> 3, sub = r & 7;
        float z[32];
#pragma unroll
        for (int c = 0; c < 32; c++) z[c] = hs[s*512 + c*16 + pos];
        float zz = 0.f;
#pragma unroll
        for (int c = 0; c < 32; c++) zz = fmaf(z[c], z[c], zz);
        float bd = INFINITY; int bi = 0;
        for (int k = sub; k < KCB; k += 8) {
            float dot = 0.f;
#pragma unroll
            for (int c = 0; c < 32; c++) dot = fmaf(scbT[c*104 + k], z[c], dot);
            float d = zz + scbsq[k] - 2.f*dot;
            if (d < bd) { bd = d; bi = k; }
        }
#pragma unroll
        for (int off = 4; off; off >>= 1) {
            float od = __shfl_down_sync(full, bd, off, 8);
            int   oi = __shfl_down_sync(full, bi, off, 8);
            if (od < bd || (od == bd && oi < bi)) { bd = od; bi = oi; }
        }
        if (sub == 0) idxs[s*16 + pos] = bi;
    }
    __syncthreads();

    float vqs = 0.f;
    for (int i = tid; i < 1024; i += 256) {
        int s = i >> 9, j = i & 511, c = j >> 4, p2 = j & 15;
        float q = scb[idxs[s*16 + p2]*32 + c];
        float zv = hs[i];
        float df = q - zv;
        vqs = fmaf(df, df, vqs);
        out[RECON_OFF + (size_t)(n0+s)*512 + j] = q;
        bl[i] = fmaf(0.5f, q, zv);
    }
    vqs = wredsum(vqs);
    if ((tid & 31) == 0) wred[tid >> 5] = vqs;
    __syncthreads();
    if (tid == 0) {
        float a = 0.f;
#pragma unroll
        for (int w = 0; w < 8; w++) a += wred[w];
        atomicAdd(&g_vq, a);
    }

    {
        int o = tid & 63, hh = (tid >> 6) & 1, ss = tid >> 7;
        const float4* wp4 = (const float4*)(fc1w + o*512 + hh*256);
        const float4* bl4 = (const float4*)(bl + ss*512 + hh*256);
        float a = 0.f;
#pragma unroll 8
        for (int t = 0; t < 64; t++) {
            float4 w = wp4[t], b = bl4[t];
            a = fmaf(w.x, b.x, a); a = fmaf(w.y, b.y, a);
            a = fmaf(w.z, b.z, a); a = fmaf(w.w, b.w, a);
        }
        z1h[tid] = a;
    }
    __syncthreads();
    if (tid < 128) {
        int ss = tid >> 6, o = tid & 63;
        z1[ss*64 + o] = fmaxf(z1h[ss*128 + o] + z1h[ss*128 + 64 + o] + fc1b[o], 0.f);
    }
    __syncthreads();

    if (tid < 64) {
        int s = tid >> 5, lane = tid & 31;
        float y = -INFINITY;
        if (lane < 10) {
            const float* wp = fc2w + lane*64;
            float a = 0.f;
#pragma unroll
            for (int j = 0; j < 64; j++) a = fmaf(wp[j], z1[s*64 + j], a);
            y = a + fc2b[lane];
        }
        float m = y;
#pragma unroll
        for (int off = 16; off; off >>= 1) m = fmaxf(m, __shfl_xor_sync(full, m, off));
        float e = (lane < 10) ? expf(y - m) : 0.f;
        float ssum = e;
#pragma unroll
        for (int off = 16; off; off >>= 1) ssum += __shfl_xor_sync(full, ssum, off);
        if (lane < 10) out[LP_OFF + (size_t)(n0+s)*10 + lane] = y - m - logf(ssum);
    }
}

__global__ void k_final(float* __restrict__ out) {
    out[LOSS_OFF] = 1.25f * g_vq / (float)(B * 16 * 32);
}

// ---------------- launch ----------------
extern "C" void kernel_launch(void* const* d_in, const int* in_sizes, int n_in,
                              void* d_out, int out_size) {
    const float* x      = (const float*)d_in[0];
    const float* c1w    = (const float*)d_in[1];
    const float* c1b    = (const float*)d_in[2];
    const float* bn1s   = (const float*)d_in[3];
    const float* bn1b   = (const float*)d_in[4];
    const float* c2w    = (const float*)d_in[5];
    const float* c2b    = (const float*)d_in[6];
    const float* bn2s   = (const float*)d_in[7];
    const float* bn2b   = (const float*)d_in[8];
    const float* c3w    = (const float*)d_in[9];
    const float* c3b    = (const float*)d_in[10];
    const float* bn3s   = (const float*)d_in[11];
    const float* bn3b   = (const float*)d_in[12];
    const float* cb     = (const float*)d_in[13];
    const float* fc1w   = (const float*)d_in[14];
    const float* fc1b   = (const float*)d_in[15];
    const float* fc2w   = (const float*)d_in[16];
    const float* fc2b   = (const float*)d_in[17];
    float* out = (float*)d_out;

    cudaFuncSetAttribute(k_conv3, cudaFuncAttributeMaxDynamicSharedMemorySize, CONV3_SMEM);

    k_conv1<<<B, 256>>>(x, c1w, c1b);                              // 0 (self-repack + stat zero)
    k_stats0<<<B, 256>>>(cb, c2w, c3w);                            // 1 (+ weight repack)
    k_conv2<<<B/2, 576>>>(c2b, bn1s, bn1b);                        // 2 (r13 v10)
    k_conv3<<<B/4, 256, CONV3_SMEM>>>(c3b, bn2s, bn2b);            // 3  <- ncu capture (r13 conv3)
    k_vqfc<<<B/2, 256>>>(cb, fc1w, fc1b, fc2w, fc2b, bn3s, bn3b, out); // 4
    k_final<<<1, 1>>>(out);                                        // 5
}